// round 16
// baseline (speedup 1.0000x reference)
#include <cuda_runtime.h>
#include <cuda_fp16.h>
#include <stdint.h>

// ============================================================================
// GRU cell via legacy mma.sync (tcgen05 unavailable at plain-sm_103 PTX target).
// R16 = R15 + WARP-PRIORITY SWAP: B300 arbiter is hi-wid-first, so producer
// warps at wid 8..11 preempted consumer MMA issue during every cp.async burst
// (~640 cyc/chunk at exactly the 8-cyc cadence the tensor pipe needs).
// Producers now at wid 0..3 (lowest priority), consumers at wid 4..11.
//   r = sigmoid(x@wx_r + hid@wh_r + b...), z = sigmoid(...),
//   n = tanh((x@wx_n + bx_n) + r*(hid@wh_n + bh_n)), out = (1-z)n + z*hid
// B=8192, I=H=1024. fp16 operands, fp32 accum, 4 register accumulator slots.
// CTA tile 128x64: 8 consumer warps (32x32) + 4 producer warps (1/SMSP).
// ============================================================================

#define TM 128
#define TN 64
#define KC 128
#define STAGES 2
#define CHT 16                 // chunks per tile: 0..7 x-phase, 8..15 hid
#define NTILES 1024            // 64 m-tiles x 16 n-tiles
#define GRID 148
#define PITCH 272              // 256B row + 16B pad (conflict-free ldsm)
#define A_BYTES (128 * PITCH)              // 34816
#define WG_BYTES (64 * PITCH)              // 17408
#define STG (A_BYTES + 3 * WG_BYTES)       // 87040
#define HIDB (2048 + STAGES * STG)         // 176128: hid tile (single buffer)
#define HPITCH 272                          // 64 floats + 16B pad
#define HBYTES (128 * HPITCH)              // 34816
#define SMEM_DYN (HIDB + HBYTES)           // 210944

#define NTHREADS 384           // 4 producer warps + 8 consumer warps

// fp16 staging (device globals = allocation-free scratch)
__device__ __half g_xh[8192u * 1024u];
__device__ __half g_hh[8192u * 1024u];
__device__ __half g_wxh[3u * 1024u * 1024u];   // [g][h][i] (k contiguous)
__device__ __half g_whh[3u * 1024u * 1024u];

// ---------------------------------------------------------------- helpers ---
__device__ __forceinline__ uint32_t smem_u32(const void* p) {
    uint32_t a;
    asm("{ .reg .u64 t; cvta.to.shared.u64 t, %1; cvt.u32.u64 %0, t; }"
        : "=r"(a) : "l"(p));
    return a;
}

__device__ __forceinline__ void cp16(uint32_t dst, const void* src) {
    asm volatile("cp.async.cg.shared.global [%0], [%1], 16;\n"
                 :: "r"(dst), "l"(src));
}

__device__ __forceinline__ void ldsm4(uint32_t* r, uint32_t addr) {
    asm volatile("ldmatrix.sync.aligned.m8n8.x4.shared.b16 {%0,%1,%2,%3}, [%4];"
                 : "=r"(r[0]), "=r"(r[1]), "=r"(r[2]), "=r"(r[3]) : "r"(addr));
}

__device__ __forceinline__ void mma16816(float* c, const uint32_t* a, const uint32_t* b) {
    asm volatile(
        "mma.sync.aligned.m16n8k16.row.col.f32.f16.f16.f32 "
        "{%0,%1,%2,%3}, {%4,%5,%6,%7}, {%8,%9}, {%0,%1,%2,%3};"
        : "+f"(c[0]), "+f"(c[1]), "+f"(c[2]), "+f"(c[3])
        : "r"(a[0]), "r"(a[1]), "r"(a[2]), "r"(a[3]), "r"(b[0]), "r"(b[1]));
}

__device__ __forceinline__ float tanh_ap(float x) {
    float r;
    asm("tanh.approx.f32 %0, %1;" : "=f"(r) : "f"(x));
    return r;
}

__device__ __forceinline__ void mbar_wait(uint32_t mbar, uint32_t parity) {
    asm volatile(
        "{\n\t.reg .pred P1;\n\t"
        "WL_%=:\n\t"
        "mbarrier.try_wait.parity.acquire.cta.shared::cta.b64 P1, [%0], %1, 0x989680;\n\t"
        "@P1 bra.uni WD_%=;\n\t"
        "bra.uni WL_%=;\n\t"
        "WD_%=:\n\t}"
        :: "r"(mbar), "r"(parity) : "memory");
}

__device__ __forceinline__ void mbar_arrive(uint32_t mbar) {
    asm volatile("mbarrier.arrive.shared.b64 _, [%0];" :: "r"(mbar) : "memory");
}

// ----------------------------------------------------- merged pre-pass ------
// blocks [0, 8192): fp32 -> fp16 convert, 8 floats/thread, uint4 stores.
// blocks [8192, 14336): 6 x 1024-block weight transpose, half2-packed stores.
__global__ void k_prep(const float* __restrict__ x, const float* __restrict__ hid,
                       const float* __restrict__ wx, const float* __restrict__ wh) {
    const int b = blockIdx.x;
    if (b < 8192) {
        const float* src = (b < 4096) ? x : hid;
        __half* dst = (b < 4096) ? g_xh : g_hh;
        size_t i = ((size_t)(b & 4095) * 256 + threadIdx.x) * 8;
        float4 v0 = *reinterpret_cast<const float4*>(src + i);
        float4 v1 = *reinterpret_cast<const float4*>(src + i + 4);
        __half2 h[4];
        h[0] = __floats2half2_rn(v0.x, v0.y);
        h[1] = __floats2half2_rn(v0.z, v0.w);
        h[2] = __floats2half2_rn(v1.x, v1.y);
        h[3] = __floats2half2_rn(v1.z, v1.w);
        *reinterpret_cast<uint4*>(dst + i) = *reinterpret_cast<uint4*>(h);
        return;
    }
    __shared__ float tile[32][33];
    const int bb = b - 8192;
    const int m = bb >> 10;
    const int rem = bb & 1023;
    const int h0 = (rem & 31) * 32;
    const int i0 = (rem >> 5) * 32;
    const float* src = (m < 3) ? (wx + (size_t)m * 1048576)
                               : (wh + (size_t)(m - 3) * 1048576);
    __half* dst = ((m < 3) ? g_wxh : g_whh) + (size_t)(m % 3) * 1048576;
    const int tid = threadIdx.x;
    const int tx = tid & 31, ty = tid >> 5;     // 32 x 8
#pragma unroll
    for (int j = 0; j < 32; j += 8)
        tile[ty + j][tx] = src[(size_t)(i0 + ty + j) * 1024 + h0 + tx];
    __syncthreads();
    // tile[a][b] = W[i0+a][h0+b]; dst[h][i] = W[i][h] = tile[i_loc][h_loc].
    const int ip = tid & 15;                    // i-pair 0..15
    const int hl = tid >> 4;                    // h_local 0..15
#pragma unroll
    for (int jj = 0; jj < 2; jj++) {
        int hh = hl + jj * 16;
        __half2 v = __floats2half2_rn(tile[2 * ip][hh], tile[2 * ip + 1][hh]);
        *reinterpret_cast<__half2*>(dst + (size_t)(h0 + hh) * 1024 + i0 + 2 * ip) = v;
    }
}

// ------------------------------------------------------------- GEMM kernel ---
// SMEM: [0,1024)      bias sb[4][64] fp32 (per tile, consumer-guarded)
//       [1024,1056)   chunk mbarriers: full[s]=1024+16s, empty[s]=1032+16s
//       [1104,1120)   hid mbarriers: hfull=1104, hempty=1112
//       [2048,176128) chunk stages: A[128][PITCH] + 3 W[64][PITCH] each
//       [176128, ...) hid tile (single buffer), pitch HPITCH
// acc slots: 0=r, 1=z, 2=gx_n, 3=gh_n.  Warp grid 4(m) x 2(n), tile 32x32.
// Producers: warps 0..3 (LOWEST wid -> lowest arbiter priority; consumers'
// MMA issue outranks cp.async bursts). Consumers: warps 4..11.

template<int NS>
__device__ __forceinline__ void compute_chunk(float (&acc)[4][2][4][4],
                                              uint32_t st, int lid, int wm, int wn) {
#pragma unroll
    for (int ks = 0; ks < 8; ks++) {
        uint32_t af[2][4];
        uint32_t bf[3][2][4];
#pragma unroll
        for (int mt = 0; mt < 2; mt++) {
            uint32_t arow = wm * 32 + mt * 16 + (lid & 15);
            ldsm4(af[mt], st + arow * PITCH + ks * 32 + (lid >> 4) * 16);
        }
#pragma unroll
        for (int g = 0; g < 3; g++)
#pragma unroll
            for (int p = 0; p < 2; p++) {
                uint32_t wrow = wn * 32 + p * 16 + (lid & 7) + ((lid & 16) >> 1);
                ldsm4(bf[g][p], st + A_BYTES + g * WG_BYTES + wrow * PITCH
                                 + ((lid >> 3) & 1) * 16 + ks * 32);
            }
#pragma unroll
        for (int g = 0; g < 3; g++) {
            const int slot = (g == 0) ? 0 : (g == 1) ? 1 : NS;
#pragma unroll
            for (int mt = 0; mt < 2; mt++)
#pragma unroll
                for (int nt = 0; nt < 4; nt++)
                    mma16816(acc[slot][mt][nt], af[mt], &bf[g][nt >> 1][(nt & 1) * 2]);
        }
    }
}

__global__ void __launch_bounds__(NTHREADS, 1)
k_gru(const float* __restrict__ hid,
      const float* __restrict__ bx, const float* __restrict__ bh,
      float* __restrict__ out) {
    extern __shared__ char smem[];
    const uint32_t sbase = smem_u32(smem);
    const uint32_t mb0 = sbase + 1024;
    const uint32_t hmb = sbase + 1104;
    const uint32_t stg0 = sbase + 2048;

    const int tid = threadIdx.x;
    const int lid = tid & 31;
    const int wid = tid >> 5;
    const int bid = blockIdx.x;

    if (tid < STAGES) {
        asm volatile("mbarrier.init.shared.b64 [%0], 128;" :: "r"(mb0 + tid * 16)     : "memory");
        asm volatile("mbarrier.init.shared.b64 [%0], 8;"   :: "r"(mb0 + tid * 16 + 8) : "memory");
    }
    if (tid == 32) {
        asm volatile("mbarrier.init.shared.b64 [%0], 128;" :: "r"(hmb)     : "memory");
        asm volatile("mbarrier.init.shared.b64 [%0], 8;"   :: "r"(hmb + 8) : "memory");
    }
    __syncthreads();

    if (wid < 4) {
        // ------- producer warps (wid 0..3 = lowest arbiter priority) -----------
        const int ptid = tid;                      // 0..127
        int c = 0;                                 // global chunk counter
        int tt = 0;                                // tile sequence counter
        for (int t = bid; t < NTILES; t += GRID, ++tt) {
            const int m0 = (t >> 4) * TM;
            const int n0 = (t & 15) * TN;
            for (int it = 0; it < CHT; ++it, ++c) {
                // deferred hid staging: by it==2, previous tile's epilogue
                // (which signals hempty) has completed -> never stalls the ring.
                if (it == 2) {
                    if (tt > 0) mbar_wait(hmb + 8, (tt - 1) & 1);   // hempty
                    uint32_t hdst = sbase + HIDB;
#pragma unroll
                    for (int q = 0; q < 16; q++) {  // 2048 cp16: 128 rows x 256B
                        int op = ptid + q * 128, row = op >> 4, cg = op & 15;
                        cp16(hdst + row * HPITCH + cg * 16,
                             hid + (size_t)(m0 + row) * 1024 + n0 + cg * 4);
                    }
                    asm volatile("cp.async.mbarrier.arrive.noinc.shared::cta.b64 [%0];"
                                 :: "r"(hmb) : "memory");           // hfull
                }
                const int s = c & 1;
                const int rnd = c >> 1;
                if (rnd > 0) mbar_wait(mb0 + s * 16 + 8, (rnd - 1) & 1);  // empty[s]
                uint32_t st = stg0 + (uint32_t)s * STG;
                const __half* asrc = (it < 8) ? g_xh  : g_hh;
                const __half* wsrc = (it < 8) ? g_wxh : g_whh;
                const int k0 = (it & 7) * KC;
#pragma unroll
                for (int q = 0; q < 16; q++) {     // A: 2048 cp16
                    int op = ptid + q * 128, row = op >> 4, cg = op & 15;
                    cp16(st + row * PITCH + cg * 16,
                         asrc + (size_t)(m0 + row) * 1024 + k0 + cg * 8);
                }
#pragma unroll
                for (int q = 0; q < 24; q++) {     // W: 3072 cp16
                    int op = ptid + q * 128, g = op >> 10, rr2 = (op >> 4) & 63, cg = op & 15;
                    cp16(st + A_BYTES + g * WG_BYTES + rr2 * PITCH + cg * 16,
                         wsrc + (size_t)g * 1048576 + (size_t)(n0 + rr2) * 1024 + k0 + cg * 8);
                }
                asm volatile("cp.async.mbarrier.arrive.noinc.shared::cta.b64 [%0];"
                             :: "r"(mb0 + s * 16) : "memory");
            }
        }
        return;
    }

    // --------------- consumer warps (wid 4..11, 256 threads) ------------------
    const int cwid = wid - 4;
    const int wm = cwid & 3;
    const int wn = cwid >> 2;
    float* sb = reinterpret_cast<float*>(smem);
    const int g4 = lid >> 2, t4 = lid & 3;

    int c = 0;
    int tt = 0;
    for (int t = bid; t < NTILES; t += GRID, ++tt) {
        const int m0 = (t >> 4) * TM;
        const int n0 = (t & 15) * TN;

        // guard: previous tile's epilogue (sb readers) done before rewrite
        asm volatile("bar.sync 1, 256;" ::: "memory");
        if (tid >= 128 && tid < 192) {
            int h = n0 + (tid - 128);
            int hl = tid - 128;
            sb[hl]        = bx[h]        + bh[h];
            sb[64 + hl]   = bx[1024 + h] + bh[1024 + h];
            sb[128 + hl]  = bx[2048 + h];
            sb[192 + hl]  = bh[2048 + h];
        }
        asm volatile("bar.sync 1, 256;" ::: "memory");

        float acc[4][2][4][4];
#pragma unroll
        for (int s = 0; s < 4; s++)
#pragma unroll
            for (int mt = 0; mt < 2; mt++)
#pragma unroll
                for (int nt = 0; nt < 4; nt++)
#pragma unroll
                    for (int q = 0; q < 4; q++) acc[s][mt][nt][q] = 0.f;

#pragma unroll 1
        for (int it = 0; it < 8; ++it, ++c) {      // x-phase: n-gate -> slot 2
            const int s = c & 1;
            mbar_wait(mb0 + s * 16, (c >> 1) & 1);
            compute_chunk<2>(acc, stg0 + (uint32_t)s * STG, lid, wm, wn);
            if (lid == 0) mbar_arrive(mb0 + s * 16 + 8);
        }
#pragma unroll 1
        for (int it = 8; it < CHT; ++it, ++c) {    // hid-phase: n-gate -> slot 3
            const int s = c & 1;
            mbar_wait(mb0 + s * 16, (c >> 1) & 1);
            compute_chunk<3>(acc, stg0 + (uint32_t)s * STG, lid, wm, wn);
            if (lid == 0) mbar_arrive(mb0 + s * 16 + 8);
        }

        // ---- fused GRU epilogue (hid from SMEM; producers stream next tile) ----
        mbar_wait(hmb, tt & 1);                    // hfull, completion #tt
        const char* hbuf = smem + HIDB;
#pragma unroll
        for (int mt = 0; mt < 2; mt++)
#pragma unroll
            for (int nt = 0; nt < 4; nt++)
#pragma unroll
                for (int hf = 0; hf < 2; hf++) {
                    int rloc = wm * 32 + mt * 16 + g4 + hf * 8;
                    int coll = wn * 32 + nt * 8 + t4 * 2;
                    float2 h2 = *reinterpret_cast<const float2*>(
                        hbuf + rloc * HPITCH + coll * 4);
                    size_t base = (size_t)(m0 + rloc) * 1024 + n0 + coll;
                    float o[2];
#pragma unroll
                    for (int j = 0; j < 2; j++) {
                        int ri = hf * 2 + j;
                        float pr = acc[0][mt][nt][ri] + sb[coll + j];
                        float pz = acc[1][mt][nt][ri] + sb[64 + coll + j];
                        // sigmoid(x) = 0.5*tanh(x/2) + 0.5 (MUFU.TANH)
                        float rr = fmaf(tanh_ap(0.5f * pr), 0.5f, 0.5f);
                        float zz = fmaf(tanh_ap(0.5f * pz), 0.5f, 0.5f);
                        float pn = (acc[2][mt][nt][ri] + sb[128 + coll + j])
                                 + rr * (acc[3][mt][nt][ri] + sb[192 + coll + j]);
                        float nn = tanh_ap(pn);    // MUFU.TANH
                        float hv = j ? h2.y : h2.x;
                        o[j] = nn + zz * (hv - nn);
                    }
                    *reinterpret_cast<float2*>(out + base) = make_float2(o[0], o[1]);
                }
        if (lid == 0) mbar_arrive(hmb + 8);        // hempty
    }
}

// --------------------------------------------------------------- launcher ---
extern "C" void kernel_launch(void* const* d_in, const int* in_sizes, int n_in,
                              void* d_out, int out_size) {
    const float* x   = (const float*)d_in[0];
    const float* hid = (const float*)d_in[1];
    const float* wx  = (const float*)d_in[2];
    const float* wh  = (const float*)d_in[3];
    const float* bx  = (const float*)d_in[4];
    const float* bh  = (const float*)d_in[5];
    float* out = (float*)d_out;

    cudaFuncSetAttribute(k_gru, cudaFuncAttributeMaxDynamicSharedMemorySize, SMEM_DYN);

    // merged pre-pass: 8192 convert blocks + 6144 weight-transpose blocks
    k_prep<<<14336, 256>>>(x, hid, wx, wh);
    k_gru<<<GRID, NTHREADS, SMEM_DYN>>>(hid, bx, bh, out);
}

// round 17
// speedup vs baseline: 1.0507x; 1.0507x over previous
#include <cuda_runtime.h>
#include <cuda_fp16.h>
#include <stdint.h>

// ============================================================================
// GRU cell via legacy mma.sync (tcgen05 unavailable at plain-sm_103 PTX target).
// R17 = R15 (best: 262.7 us; R16 priority-swap REVERTED — producers need the
// hi-wid arbiter priority to stay ahead) + producer-staged biases: the 6 bias
// segments ride the hid-tile cp.async batch under the hfull/hempty handshake,
// deleting 2 bar.syncs + 4 strided gmem loads per tile from consumer warps.
//   r = sigmoid(x@wx_r + hid@wh_r + b...), z = sigmoid(...),
//   n = tanh((x@wx_n + bx_n) + r*(hid@wh_n + bh_n)), out = (1-z)n + z*hid
// B=8192, I=H=1024. fp16 operands, fp32 accum, 4 register accumulator slots.
// CTA tile 128x64: 8 consumer warps (32x32, wid 0..7) + 4 producer warps
// (wid 8..11, one per SMSP). Persistent grid of 148.
// ============================================================================

#define TM 128
#define TN 64
#define KC 128
#define STAGES 2
#define CHT 16                 // chunks per tile: 0..7 x-phase, 8..15 hid
#define NTILES 1024            // 64 m-tiles x 16 n-tiles
#define GRID 148
#define PITCH 272              // 256B row + 16B pad (conflict-free ldsm)
#define A_BYTES (128 * PITCH)              // 34816
#define WG_BYTES (64 * PITCH)              // 17408
#define STG (A_BYTES + 3 * WG_BYTES)       // 87040
#define HIDB (2048 + STAGES * STG)         // 176128: hid tile (single buffer)
#define HPITCH 272                          // 64 floats + 16B pad
#define HBYTES (128 * HPITCH)              // 34816
#define SMEM_DYN (HIDB + HBYTES)           // 210944

#define NTHREADS 384           // 8 consumer warps + 4 producer warps

// fp16 staging (device globals = allocation-free scratch)
__device__ __half g_xh[8192u * 1024u];
__device__ __half g_hh[8192u * 1024u];
__device__ __half g_wxh[3u * 1024u * 1024u];   // [g][h][i] (k contiguous)
__device__ __half g_whh[3u * 1024u * 1024u];

// ---------------------------------------------------------------- helpers ---
__device__ __forceinline__ uint32_t smem_u32(const void* p) {
    uint32_t a;
    asm("{ .reg .u64 t; cvta.to.shared.u64 t, %1; cvt.u32.u64 %0, t; }"
        : "=r"(a) : "l"(p));
    return a;
}

__device__ __forceinline__ void cp16(uint32_t dst, const void* src) {
    asm volatile("cp.async.cg.shared.global [%0], [%1], 16;\n"
                 :: "r"(dst), "l"(src));
}

__device__ __forceinline__ void ldsm4(uint32_t* r, uint32_t addr) {
    asm volatile("ldmatrix.sync.aligned.m8n8.x4.shared.b16 {%0,%1,%2,%3}, [%4];"
                 : "=r"(r[0]), "=r"(r[1]), "=r"(r[2]), "=r"(r[3]) : "r"(addr));
}

__device__ __forceinline__ void mma16816(float* c, const uint32_t* a, const uint32_t* b) {
    asm volatile(
        "mma.sync.aligned.m16n8k16.row.col.f32.f16.f16.f32 "
        "{%0,%1,%2,%3}, {%4,%5,%6,%7}, {%8,%9}, {%0,%1,%2,%3};"
        : "+f"(c[0]), "+f"(c[1]), "+f"(c[2]), "+f"(c[3])
        : "r"(a[0]), "r"(a[1]), "r"(a[2]), "r"(a[3]), "r"(b[0]), "r"(b[1]));
}

__device__ __forceinline__ float tanh_ap(float x) {
    float r;
    asm("tanh.approx.f32 %0, %1;" : "=f"(r) : "f"(x));
    return r;
}

__device__ __forceinline__ void mbar_wait(uint32_t mbar, uint32_t parity) {
    asm volatile(
        "{\n\t.reg .pred P1;\n\t"
        "WL_%=:\n\t"
        "mbarrier.try_wait.parity.acquire.cta.shared::cta.b64 P1, [%0], %1, 0x989680;\n\t"
        "@P1 bra.uni WD_%=;\n\t"
        "bra.uni WL_%=;\n\t"
        "WD_%=:\n\t}"
        :: "r"(mbar), "r"(parity) : "memory");
}

__device__ __forceinline__ void mbar_arrive(uint32_t mbar) {
    asm volatile("mbarrier.arrive.shared.b64 _, [%0];" :: "r"(mbar) : "memory");
}

// ----------------------------------------------------- merged pre-pass ------
// blocks [0, 8192): fp32 -> fp16 convert, 8 floats/thread, uint4 stores.
// blocks [8192, 14336): 6 x 1024-block weight transpose, half2-packed stores.
__global__ void k_prep(const float* __restrict__ x, const float* __restrict__ hid,
                       const float* __restrict__ wx, const float* __restrict__ wh) {
    const int b = blockIdx.x;
    if (b < 8192) {
        const float* src = (b < 4096) ? x : hid;
        __half* dst = (b < 4096) ? g_xh : g_hh;
        size_t i = ((size_t)(b & 4095) * 256 + threadIdx.x) * 8;
        float4 v0 = *reinterpret_cast<const float4*>(src + i);
        float4 v1 = *reinterpret_cast<const float4*>(src + i + 4);
        __half2 h[4];
        h[0] = __floats2half2_rn(v0.x, v0.y);
        h[1] = __floats2half2_rn(v0.z, v0.w);
        h[2] = __floats2half2_rn(v1.x, v1.y);
        h[3] = __floats2half2_rn(v1.z, v1.w);
        *reinterpret_cast<uint4*>(dst + i) = *reinterpret_cast<uint4*>(h);
        return;
    }
    __shared__ float tile[32][33];
    const int bb = b - 8192;
    const int m = bb >> 10;
    const int rem = bb & 1023;
    const int h0 = (rem & 31) * 32;
    const int i0 = (rem >> 5) * 32;
    const float* src = (m < 3) ? (wx + (size_t)m * 1048576)
                               : (wh + (size_t)(m - 3) * 1048576);
    __half* dst = ((m < 3) ? g_wxh : g_whh) + (size_t)(m % 3) * 1048576;
    const int tid = threadIdx.x;
    const int tx = tid & 31, ty = tid >> 5;     // 32 x 8
#pragma unroll
    for (int j = 0; j < 32; j += 8)
        tile[ty + j][tx] = src[(size_t)(i0 + ty + j) * 1024 + h0 + tx];
    __syncthreads();
    // tile[a][b] = W[i0+a][h0+b]; dst[h][i] = W[i][h] = tile[i_loc][h_loc].
    const int ip = tid & 15;                    // i-pair 0..15
    const int hl = tid >> 4;                    // h_local 0..15
#pragma unroll
    for (int jj = 0; jj < 2; jj++) {
        int hh = hl + jj * 16;
        __half2 v = __floats2half2_rn(tile[2 * ip][hh], tile[2 * ip + 1][hh]);
        *reinterpret_cast<__half2*>(dst + (size_t)(h0 + hh) * 1024 + i0 + 2 * ip) = v;
    }
}

// ------------------------------------------------------------- GEMM kernel ---
// SMEM: [0,1536)      bias sb[6][64] fp32: bx_r, bx_z, bx_n, bh_r, bh_z, bh_n
//                     (cp.async-staged by producers under hfull/hempty)
//       [1536,1568)   chunk mbarriers: full[s]=1536+16s, empty[s]=1544+16s
//       [1616,1632)   hid mbarriers: hfull=1616, hempty=1624
//       [2048,176128) chunk stages: A[128][PITCH] + 3 W[64][PITCH] each
//       [176128, ...) hid tile (single buffer), pitch HPITCH
// acc slots: 0=r, 1=z, 2=gx_n, 3=gh_n.  Warp grid 4(m) x 2(n), tile 32x32.
// Producers: warps 8..11 (hi-wid = hi arbiter priority, per R15/R16 evidence).

template<int NS>
__device__ __forceinline__ void compute_chunk(float (&acc)[4][2][4][4],
                                              uint32_t st, int lid, int wm, int wn) {
#pragma unroll
    for (int ks = 0; ks < 8; ks++) {
        uint32_t af[2][4];
        uint32_t bf[3][2][4];
#pragma unroll
        for (int mt = 0; mt < 2; mt++) {
            uint32_t arow = wm * 32 + mt * 16 + (lid & 15);
            ldsm4(af[mt], st + arow * PITCH + ks * 32 + (lid >> 4) * 16);
        }
#pragma unroll
        for (int g = 0; g < 3; g++)
#pragma unroll
            for (int p = 0; p < 2; p++) {
                uint32_t wrow = wn * 32 + p * 16 + (lid & 7) + ((lid & 16) >> 1);
                ldsm4(bf[g][p], st + A_BYTES + g * WG_BYTES + wrow * PITCH
                                 + ((lid >> 3) & 1) * 16 + ks * 32);
            }
#pragma unroll
        for (int g = 0; g < 3; g++) {
            const int slot = (g == 0) ? 0 : (g == 1) ? 1 : NS;
#pragma unroll
            for (int mt = 0; mt < 2; mt++)
#pragma unroll
                for (int nt = 0; nt < 4; nt++)
                    mma16816(acc[slot][mt][nt], af[mt], &bf[g][nt >> 1][(nt & 1) * 2]);
        }
    }
}

__global__ void __launch_bounds__(NTHREADS, 1)
k_gru(const float* __restrict__ hid,
      const float* __restrict__ bx, const float* __restrict__ bh,
      float* __restrict__ out) {
    extern __shared__ char smem[];
    const uint32_t sbase = smem_u32(smem);
    const uint32_t mb0 = sbase + 1536;
    const uint32_t hmb = sbase + 1616;
    const uint32_t stg0 = sbase + 2048;

    const int tid = threadIdx.x;
    const int lid = tid & 31;
    const int wid = tid >> 5;
    const int bid = blockIdx.x;

    if (tid < STAGES) {
        asm volatile("mbarrier.init.shared.b64 [%0], 128;" :: "r"(mb0 + tid * 16)     : "memory");
        asm volatile("mbarrier.init.shared.b64 [%0], 8;"   :: "r"(mb0 + tid * 16 + 8) : "memory");
    }
    if (tid == 32) {
        asm volatile("mbarrier.init.shared.b64 [%0], 128;" :: "r"(hmb)     : "memory");
        asm volatile("mbarrier.init.shared.b64 [%0], 8;"   :: "r"(hmb + 8) : "memory");
    }
    __syncthreads();

    if (wid >= 8) {
        // ------- producer warps (wid 8..11, one per SMSP, hi priority) ---------
        const int ptid = tid - 256;               // 0..127
        int c = 0;                                 // global chunk counter
        int tt = 0;                                // tile sequence counter
        for (int t = bid; t < NTILES; t += GRID, ++tt) {
            const int m0 = (t >> 4) * TM;
            const int n0 = (t & 15) * TN;
            for (int it = 0; it < CHT; ++it, ++c) {
                // deferred hid+bias staging: by it==2, previous tile's epilogue
                // (which signals hempty) has completed -> never stalls the ring.
                if (it == 2) {
                    if (tt > 0) mbar_wait(hmb + 8, (tt - 1) & 1);   // hempty
                    uint32_t hdst = sbase + HIDB;
#pragma unroll
                    for (int q = 0; q < 16; q++) {  // 2048 cp16: 128 rows x 256B
                        int op = ptid + q * 128, row = op >> 4, cg = op & 15;
                        cp16(hdst + row * HPITCH + cg * 16,
                             hid + (size_t)(m0 + row) * 1024 + n0 + cg * 4);
                    }
                    // bias segments: sb[seg][64], seg 0..2 = bx gates, 3..5 = bh
                    if (ptid < 96) {
                        int seg = ptid >> 4, cg = ptid & 15;
                        const float* bsrc = (seg < 3) ? bx : bh;
                        cp16(sbase + ptid * 16,
                             bsrc + (seg % 3) * 1024 + n0 + cg * 4);
                    }
                    asm volatile("cp.async.mbarrier.arrive.noinc.shared::cta.b64 [%0];"
                                 :: "r"(hmb) : "memory");           // hfull
                }
                const int s = c & 1;
                const int rnd = c >> 1;
                if (rnd > 0) mbar_wait(mb0 + s * 16 + 8, (rnd - 1) & 1);  // empty[s]
                uint32_t st = stg0 + (uint32_t)s * STG;
                const __half* asrc = (it < 8) ? g_xh  : g_hh;
                const __half* wsrc = (it < 8) ? g_wxh : g_whh;
                const int k0 = (it & 7) * KC;
#pragma unroll
                for (int q = 0; q < 16; q++) {     // A: 2048 cp16
                    int op = ptid + q * 128, row = op >> 4, cg = op & 15;
                    cp16(st + row * PITCH + cg * 16,
                         asrc + (size_t)(m0 + row) * 1024 + k0 + cg * 8);
                }
#pragma unroll
                for (int q = 0; q < 24; q++) {     // W: 3072 cp16
                    int op = ptid + q * 128, g = op >> 10, rr2 = (op >> 4) & 63, cg = op & 15;
                    cp16(st + A_BYTES + g * WG_BYTES + rr2 * PITCH + cg * 16,
                         wsrc + (size_t)g * 1048576 + (size_t)(n0 + rr2) * 1024 + k0 + cg * 8);
                }
                asm volatile("cp.async.mbarrier.arrive.noinc.shared::cta.b64 [%0];"
                             :: "r"(mb0 + s * 16) : "memory");
            }
        }
        return;
    }

    // ------------------- consumer warps (wid 0..7, 256 threads) ---------------
    const int wm = wid & 3;
    const int wn = wid >> 2;
    const float* sb = reinterpret_cast<const float*>(smem);
    const int g4 = lid >> 2, t4 = lid & 3;

    int c = 0;
    int tt = 0;
    for (int t = bid; t < NTILES; t += GRID, ++tt) {
        const int m0 = (t >> 4) * TM;
        const int n0 = (t & 15) * TN;

        float acc[4][2][4][4];
#pragma unroll
        for (int s = 0; s < 4; s++)
#pragma unroll
            for (int mt = 0; mt < 2; mt++)
#pragma unroll
                for (int nt = 0; nt < 4; nt++)
#pragma unroll
                    for (int q = 0; q < 4; q++) acc[s][mt][nt][q] = 0.f;

#pragma unroll 1
        for (int it = 0; it < 8; ++it, ++c) {      // x-phase: n-gate -> slot 2
            const int s = c & 1;
            mbar_wait(mb0 + s * 16, (c >> 1) & 1);
            compute_chunk<2>(acc, stg0 + (uint32_t)s * STG, lid, wm, wn);
            if (lid == 0) mbar_arrive(mb0 + s * 16 + 8);
        }
#pragma unroll 1
        for (int it = 8; it < CHT; ++it, ++c) {    // hid-phase: n-gate -> slot 3
            const int s = c & 1;
            mbar_wait(mb0 + s * 16, (c >> 1) & 1);
            compute_chunk<3>(acc, stg0 + (uint32_t)s * STG, lid, wm, wn);
            if (lid == 0) mbar_arrive(mb0 + s * 16 + 8);
        }

        // ---- fused GRU epilogue (hid + biases from SMEM, staged by producers) --
        mbar_wait(hmb, tt & 1);                    // hfull, completion #tt
        const char* hbuf = smem + HIDB;
#pragma unroll
        for (int mt = 0; mt < 2; mt++)
#pragma unroll
            for (int nt = 0; nt < 4; nt++)
#pragma unroll
                for (int hf = 0; hf < 2; hf++) {
                    int rloc = wm * 32 + mt * 16 + g4 + hf * 8;
                    int coll = wn * 32 + nt * 8 + t4 * 2;
                    float2 h2 = *reinterpret_cast<const float2*>(
                        hbuf + rloc * HPITCH + coll * 4);
                    size_t base = (size_t)(m0 + rloc) * 1024 + n0 + coll;
                    float o[2];
#pragma unroll
                    for (int j = 0; j < 2; j++) {
                        int ri = hf * 2 + j;
                        int cj = coll + j;
                        float pr = acc[0][mt][nt][ri] + sb[cj]       + sb[192 + cj];
                        float pz = acc[1][mt][nt][ri] + sb[64 + cj]  + sb[256 + cj];
                        // sigmoid(x) = 0.5*tanh(x/2) + 0.5 (MUFU.TANH)
                        float rr = fmaf(tanh_ap(0.5f * pr), 0.5f, 0.5f);
                        float zz = fmaf(tanh_ap(0.5f * pz), 0.5f, 0.5f);
                        float pn = (acc[2][mt][nt][ri] + sb[128 + cj])
                                 + rr * (acc[3][mt][nt][ri] + sb[320 + cj]);
                        float nn = tanh_ap(pn);    // MUFU.TANH
                        float hv = j ? h2.y : h2.x;
                        o[j] = nn + zz * (hv - nn);
                    }
                    *reinterpret_cast<float2*>(out + base) = make_float2(o[0], o[1]);
                }
        if (lid == 0) mbar_arrive(hmb + 8);        // hempty
    }
}

// --------------------------------------------------------------- launcher ---
extern "C" void kernel_launch(void* const* d_in, const int* in_sizes, int n_in,
                              void* d_out, int out_size) {
    const float* x   = (const float*)d_in[0];
    const float* hid = (const float*)d_in[1];
    const float* wx  = (const float*)d_in[2];
    const float* wh  = (const float*)d_in[3];
    const float* bx  = (const float*)d_in[4];
    const float* bh  = (const float*)d_in[5];
    float* out = (float*)d_out;

    cudaFuncSetAttribute(k_gru, cudaFuncAttributeMaxDynamicSharedMemorySize, SMEM_DYN);

    // merged pre-pass: 8192 convert blocks + 6144 weight-transpose blocks
    k_prep<<<14336, 256>>>(x, hid, wx, wh);
    k_gru<<<GRID, NTHREADS, SMEM_DYN>>>(hid, bx, bh, out);
}